// round 5
// baseline (speedup 1.0000x reference)
#include <cuda_runtime.h>
#include <math.h>
#include <float.h>

// ---------------------------------------------------------------------------
// EdgeConv-style GNN block:
//   layer1 factorized over nodes:  pre1(e) = A[tgt] + B[src]
//       A = x @ (W1a - W1b)^T + b1,   B = x @ W1b^T
//   layer2 fused per-message GEMM:  z = relu(pre1) @ W2'^T + c2
//       (BN1 scale folded into W2', BN1 shift folded into c2)
//   epilogue: h2 = BN2(relu(z)) -> atomic float max into agg[tgt]
//   layer3: out = BN3(relu(agg @ W3^T + b3))
// ---------------------------------------------------------------------------

#define C_IN   128
#define C_OUT  256
#define TM     64     // rows (messages/nodes) per CTA
#define KC     64     // K chunk
#define NTHR   256
#define SVS    65     // float2 row stride for staged V tile (64 + 1 pad)
#define BN_EPS 1e-5f
#define MAXN   20000
#define MAXE   640000

// ---- static device scratch (no runtime allocation allowed) ----------------
static __device__ __align__(128) float g_AB [(size_t)MAXN * 2 * C_OUT]; // [node][0:256)=A,[256:512)=B
static __device__ __align__(128) float g_agg[(size_t)MAXN * C_OUT];     // segment-max accumulator
static __device__ __align__(128) float g_Wct[C_IN * 2 * C_OUT];         // [k][j] layer-1 weights (j<256:A else B)
static __device__ __align__(128) float g_W2t[C_OUT * C_OUT];            // [k][n] = W2[n][k] * s1[k]
static __device__ __align__(128) float g_W3t[C_OUT * C_OUT];            // [k][n] = W3[n][k]
static __device__ __align__(128) float g_c2 [C_OUT];                    // W2 @ t1 + b2
static __device__ __align__(128) float g_s2 [C_OUT], g_t2[C_OUT];
static __device__ __align__(128) float g_s3 [C_OUT], g_t3[C_OUT];
static __device__ __align__(128) int   g_src[MAXE], g_tgt[MAXE];
static __device__ int g_idx64;

// ---- packed fp32x2 FMA (FFMA2) ---------------------------------------------
__device__ __forceinline__ unsigned long long fma2(unsigned long long a,
                                                   unsigned long long b,
                                                   unsigned long long c) {
    unsigned long long d;
    asm("fma.rn.f32x2 %0, %1, %2, %3;" : "=l"(d) : "l"(a), "l"(b), "l"(c));
    return d;
}
__device__ __forceinline__ float2 unpack2(unsigned long long u) {
    float2 f;
    asm("mov.b64 {%0, %1}, %2;" : "=f"(f.x), "=f"(f.y) : "l"(u));
    return f;
}

// ordered-int trick for float atomic max (sign-bit based, handles +-0)
__device__ __forceinline__ void atomicMaxF(float* a, float v) {
    int bits = __float_as_int(v);
    if (bits >= 0) atomicMax((int*)a, bits);
    else           atomicMin((unsigned int*)a, (unsigned int)bits);
}

// ---- shared GEMM inner loop -------------------------------------------------
// Warp mg owns rows [mg*8, mg*8+8); lane ng owns cols [ng*8, ng*8+8).
// sV2 holds each activation duplicated as (v,v) so FFMA2 needs no packing MOVs.
__device__ __forceinline__ void gemm_chunk(const float2* __restrict__ sV2,
                                           const float* __restrict__ sW,
                                           unsigned long long acc[8][4],
                                           int mg, int ng) {
    const float2* vbase = sV2 + mg * 8 * SVS;
    const unsigned long long* wbase =
        reinterpret_cast<const unsigned long long*>(sW + ng * 8);
#pragma unroll 4
    for (int k = 0; k < KC; ++k) {
        unsigned long long w0 = wbase[k * 128 + 0];
        unsigned long long w1 = wbase[k * 128 + 1];
        unsigned long long w2 = wbase[k * 128 + 2];
        unsigned long long w3 = wbase[k * 128 + 3];
#pragma unroll
        for (int i = 0; i < 8; ++i) {
            unsigned long long vv =
                *reinterpret_cast<const unsigned long long*>(vbase + i * SVS + k);
            acc[i][0] = fma2(vv, w0, acc[i][0]);
            acc[i][1] = fma2(vv, w1, acc[i][1]);
            acc[i][2] = fma2(vv, w2, acc[i][2]);
            acc[i][3] = fma2(vv, w3, acc[i][3]);
        }
    }
}

__device__ __forceinline__ void load_w_chunk(float* sW, const float* __restrict__ gW,
                                             int rowStride, int tid) {
    for (int t = tid; t < KC * (C_OUT / 4); t += NTHR) {
        int kk = t >> 6;
        int c4 = t & 63;
        *(float4*)(sW + kk * C_OUT + (c4 << 2)) =
            *(const float4*)(gW + (size_t)kk * rowStride + (c4 << 2));
    }
}

// ---- edge index dtype detection + decode ------------------------------------
// If source data is little-endian int64 with values < 2^31, every odd 32-bit
// word is zero. Random int32 indices make that pattern vanishingly unlikely.
__global__ void detect_idx(const int* __restrict__ p) {
    if (threadIdx.x == 0) {
        int is64 = 1;
        for (int i = 0; i < 64; ++i)
            if (p[2 * i + 1] != 0) { is64 = 0; break; }
        g_idx64 = is64;
    }
}

__global__ void decode_idx(const void* __restrict__ idxRaw, long long E2, int Nn) {
    long long i = (long long)blockIdx.x * blockDim.x + threadIdx.x;
    if (i >= E2) return;
    int v;
    if (g_idx64) v = (int)((const long long*)idxRaw)[i];
    else         v = ((const int*)idxRaw)[i];
    if (v < 0) v = 0;
    if (v >= Nn) v = Nn - 1;
    long long E = E2 >> 1;
    if (i < E) g_src[i] = v;
    else       g_tgt[i - E] = v;
}

// ---- prep kernels -----------------------------------------------------------
__global__ void prep_bn(const float* g1, const float* be1, const float* m1, const float* v1,
                        const float* W2, const float* b2,
                        const float* g2, const float* be2, const float* m2, const float* v2,
                        const float* g3, const float* be3, const float* m3, const float* v3) {
    int c = threadIdx.x;
    float s2 = g2[c] * rsqrtf(v2[c] + BN_EPS);
    g_s2[c] = s2;  g_t2[c] = be2[c] - m2[c] * s2;
    float s3 = g3[c] * rsqrtf(v3[c] + BN_EPS);
    g_s3[c] = s3;  g_t3[c] = be3[c] - m3[c] * s3;
    float acc = b2[c];
    for (int k = 0; k < C_OUT; ++k) {
        float s1 = g1[k] * rsqrtf(v1[k] + BN_EPS);
        float t1 = be1[k] - m1[k] * s1;
        acc += W2[c * C_OUT + k] * t1;
    }
    g_c2[c] = acc;
}

__global__ void prep_w(const float* W1, const float* W2, const float* W3,
                       const float* g1, const float* v1) {
    int i = blockIdx.x * blockDim.x + threadIdx.x;
    if (i < C_IN * 2 * C_OUT) {           // 128 x 512
        int k = i / (2 * C_OUT), j = i % (2 * C_OUT);
        float val;
        if (j < C_OUT)
            val = W1[j * (2 * C_IN) + k] - W1[j * (2 * C_IN) + C_IN + k];   // A weights
        else
            val = W1[(j - C_OUT) * (2 * C_IN) + C_IN + k];                  // B weights
        g_Wct[i] = val;
    }
    if (i < C_OUT * C_OUT) {              // 256 x 256
        int k = i / C_OUT, n = i % C_OUT;
        float s1 = g1[k] * rsqrtf(v1[k] + BN_EPS);
        g_W2t[i] = W2[n * C_OUT + k] * s1;
        g_W3t[i] = W3[n * C_OUT + k];
    }
}

__global__ void init_agg(int total) {
    int i = blockIdx.x * blockDim.x + threadIdx.x;
    if (i < total) g_agg[i] = -FLT_MAX;
}

// ---- kernel 1: node GEMM -> A|B table  (M=N_nodes, K=128, N=512) -----------
__global__ void __launch_bounds__(NTHR, 2)
k1_node_gemm(const float* __restrict__ x, const float* __restrict__ b1, int Nn) {
    extern __shared__ float sh[];
    float2* sV2 = (float2*)sh;
    float*  sW  = sh + TM * SVS * 2;
    int tid = threadIdx.x;
    int mg = tid >> 5, ng = tid & 31;
    int row = tid >> 2, q = tid & 3;
    int m0 = blockIdx.x * TM;
    int jh = blockIdx.y;                       // 0: A half, 1: B half
    int node = m0 + row; if (node >= Nn) node = Nn - 1;

    unsigned long long acc[8][4];
#pragma unroll
    for (int i = 0; i < 8; ++i)
#pragma unroll
        for (int p = 0; p < 4; ++p) acc[i][p] = 0ull;

    for (int kc = 0; kc < C_IN; kc += KC) {
        load_w_chunk(sW, g_Wct + (size_t)kc * (2 * C_OUT) + jh * C_OUT, 2 * C_OUT, tid);
        const float4* xr = (const float4*)(x + (size_t)node * C_IN + kc) + q * 4;
        float2* d = sV2 + row * SVS + q * 16;
#pragma unroll
        for (int j = 0; j < 4; ++j) {
            float4 v = xr[j];
            d[j * 4 + 0] = make_float2(v.x, v.x);
            d[j * 4 + 1] = make_float2(v.y, v.y);
            d[j * 4 + 2] = make_float2(v.z, v.z);
            d[j * 4 + 3] = make_float2(v.w, v.w);
        }
        __syncthreads();
        gemm_chunk(sV2, sW, acc, mg, ng);
        __syncthreads();
    }

    int n0 = ng * 8;
#pragma unroll
    for (int i = 0; i < 8; ++i) {
        int nd = m0 + mg * 8 + i;
        if (nd >= Nn) break;
        float* dst = g_AB + (size_t)nd * (2 * C_OUT) + jh * C_OUT + n0;
#pragma unroll
        for (int p = 0; p < 4; ++p) {
            float2 z = unpack2(acc[i][p]);
            if (jh == 0) {
                z.x += __ldg(&b1[n0 + 2 * p]);
                z.y += __ldg(&b1[n0 + 2 * p + 1]);
            }
            dst[2 * p]     = z.x;
            dst[2 * p + 1] = z.y;
        }
    }
}

// ---- kernel 2: fused message GEMM + BN2/ReLU + atomic segment max ----------
__global__ void __launch_bounds__(NTHR, 2)
k2_edge_gemm(long long E, int Nn) {
    extern __shared__ float sh[];
    float2* sV2 = (float2*)sh;
    float*  sW  = sh + TM * SVS * 2;
    __shared__ int sSrc[TM], sTgt[TM];

    int tid = threadIdx.x;
    int mg = tid >> 5, ng = tid & 31;
    int row = tid >> 2, q = tid & 3;
    long long EN = E + (long long)Nn;
    long long m0 = (long long)blockIdx.x * TM;

    if (tid < TM) {
        long long m = m0 + tid;
        int s = 0, t = 0;
        if (m < E)        { s = g_src[m];  t = g_tgt[m]; }
        else if (m < EN)  { s = t = (int)(m - E); }           // self loops
        sSrc[tid] = s;  sTgt[tid] = t;
    }

    unsigned long long acc[8][4];
#pragma unroll
    for (int i = 0; i < 8; ++i)
#pragma unroll
        for (int p = 0; p < 4; ++p) acc[i][p] = 0ull;

    __syncthreads();
    const float* Ar = g_AB + (size_t)sTgt[row] * (2 * C_OUT);
    const float* Br = g_AB + (size_t)sSrc[row] * (2 * C_OUT) + C_OUT;

    for (int kc = 0; kc < C_OUT; kc += KC) {
        load_w_chunk(sW, g_W2t + (size_t)kc * C_OUT, C_OUT, tid);
        const float4* ar = (const float4*)(Ar + kc) + q * 4;
        const float4* br = (const float4*)(Br + kc) + q * 4;
        float2* d = sV2 + row * SVS + q * 16;
#pragma unroll
        for (int j = 0; j < 4; ++j) {
            float4 a = ar[j], b = br[j];
            float vx = fmaxf(a.x + b.x, 0.0f);
            float vy = fmaxf(a.y + b.y, 0.0f);
            float vz = fmaxf(a.z + b.z, 0.0f);
            float vw = fmaxf(a.w + b.w, 0.0f);
            d[j * 4 + 0] = make_float2(vx, vx);
            d[j * 4 + 1] = make_float2(vy, vy);
            d[j * 4 + 2] = make_float2(vz, vz);
            d[j * 4 + 3] = make_float2(vw, vw);
        }
        __syncthreads();
        gemm_chunk(sV2, sW, acc, mg, ng);
        __syncthreads();
    }

    int n0 = ng * 8;
    float c2v[8], s2v[8], t2v[8];
#pragma unroll
    for (int u = 0; u < 8; ++u) {
        c2v[u] = __ldg(&g_c2[n0 + u]);
        s2v[u] = __ldg(&g_s2[n0 + u]);
        t2v[u] = __ldg(&g_t2[n0 + u]);
    }
#pragma unroll
    for (int i = 0; i < 8; ++i) {
        long long m = m0 + mg * 8 + i;
        if (m >= EN) break;
        float* dst = g_agg + (size_t)sTgt[mg * 8 + i] * C_OUT + n0;
#pragma unroll
        for (int p = 0; p < 4; ++p) {
            float2 z = unpack2(acc[i][p]);
            float h0 = fmaxf(z.x + c2v[2 * p],     0.0f) * s2v[2 * p]     + t2v[2 * p];
            float h1 = fmaxf(z.y + c2v[2 * p + 1], 0.0f) * s2v[2 * p + 1] + t2v[2 * p + 1];
            atomicMaxF(dst + 2 * p,     h0);
            atomicMaxF(dst + 2 * p + 1, h1);
        }
    }
}

// ---- kernel 3: out = BN3(relu(agg @ W3^T + b3)) -----------------------------
__global__ void __launch_bounds__(NTHR, 2)
k3_out_gemm(const float* __restrict__ b3, float* __restrict__ out, int Nn) {
    extern __shared__ float sh[];
    float2* sV2 = (float2*)sh;
    float*  sW  = sh + TM * SVS * 2;
    int tid = threadIdx.x;
    int mg = tid >> 5, ng = tid & 31;
    int row = tid >> 2, q = tid & 3;
    int m0 = blockIdx.x * TM;
    int node = m0 + row; if (node >= Nn) node = Nn - 1;

    unsigned long long acc[8][4];
#pragma unroll
    for (int i = 0; i < 8; ++i)
#pragma unroll
        for (int p = 0; p < 4; ++p) acc[i][p] = 0ull;

    const float* Ar = g_agg + (size_t)node * C_OUT;
    for (int kc = 0; kc < C_OUT; kc += KC) {
        load_w_chunk(sW, g_W3t + (size_t)kc * C_OUT, C_OUT, tid);
        const float4* ar = (const float4*)(Ar + kc) + q * 4;
        float2* d = sV2 + row * SVS + q * 16;
#pragma unroll
        for (int j = 0; j < 4; ++j) {
            float4 v = ar[j];
            d[j * 4 + 0] = make_float2(v.x, v.x);
            d[j * 4 + 1] = make_float2(v.y, v.y);
            d[j * 4 + 2] = make_float2(v.z, v.z);
            d[j * 4 + 3] = make_float2(v.w, v.w);
        }
        __syncthreads();
        gemm_chunk(sV2, sW, acc, mg, ng);
        __syncthreads();
    }

    int n0 = ng * 8;
    float b3v[8], s3v[8], t3v[8];
#pragma unroll
    for (int u = 0; u < 8; ++u) {
        b3v[u] = __ldg(&b3[n0 + u]);
        s3v[u] = __ldg(&g_s3[n0 + u]);
        t3v[u] = __ldg(&g_t3[n0 + u]);
    }
#pragma unroll
    for (int i = 0; i < 8; ++i) {
        int nd = m0 + mg * 8 + i;
        if (nd >= Nn) break;
        float* dst = out + (size_t)nd * C_OUT + n0;
#pragma unroll
        for (int p = 0; p < 4; ++p) {
            float2 z = unpack2(acc[i][p]);
            dst[2 * p]     = fmaxf(z.x + b3v[2 * p],     0.0f) * s3v[2 * p]     + t3v[2 * p];
            dst[2 * p + 1] = fmaxf(z.y + b3v[2 * p + 1], 0.0f) * s3v[2 * p + 1] + t3v[2 * p + 1];
        }
    }
}

// ---------------------------------------------------------------------------
extern "C" void kernel_launch(void* const* d_in, const int* in_sizes, int n_in,
                              void* d_out, int out_size) {
    const float* x   = (const float*)d_in[0];
    const void*  idx = (const void*)d_in[1];
    const float* W1 = (const float*)d_in[2];  const float* b1 = (const float*)d_in[3];
    const float* g1 = (const float*)d_in[4];  const float* be1= (const float*)d_in[5];
    const float* m1 = (const float*)d_in[6];  const float* v1 = (const float*)d_in[7];
    const float* W2 = (const float*)d_in[8];  const float* b2 = (const float*)d_in[9];
    const float* g2 = (const float*)d_in[10]; const float* be2= (const float*)d_in[11];
    const float* m2 = (const float*)d_in[12]; const float* v2 = (const float*)d_in[13];
    const float* W3 = (const float*)d_in[14]; const float* b3 = (const float*)d_in[15];
    const float* g3 = (const float*)d_in[16]; const float* be3= (const float*)d_in[17];
    const float* m3 = (const float*)d_in[18]; const float* v3 = (const float*)d_in[19];
    float* out = (float*)d_out;

    int Nn = in_sizes[0] / C_IN;
    long long E2 = (long long)in_sizes[1];     // 2*E logical elements
    long long E  = E2 >> 1;

    size_t shmem = (size_t)TM * SVS * sizeof(float2) + (size_t)KC * C_OUT * sizeof(float);
    cudaFuncSetAttribute(k1_node_gemm, cudaFuncAttributeMaxDynamicSharedMemorySize, (int)shmem);
    cudaFuncSetAttribute(k2_edge_gemm, cudaFuncAttributeMaxDynamicSharedMemorySize, (int)shmem);
    cudaFuncSetAttribute(k3_out_gemm,  cudaFuncAttributeMaxDynamicSharedMemorySize, (int)shmem);

    detect_idx<<<1, 32>>>((const int*)idx);
    decode_idx<<<(int)((E2 + 255) / 256), 256>>>(idx, E2, Nn);

    prep_bn<<<1, C_OUT>>>(g1, be1, m1, v1, W2, b2, g2, be2, m2, v2, g3, be3, m3, v3);
    prep_w<<<(C_IN * 2 * C_OUT + 255) / 256, 256>>>(W1, W2, W3, g1, v1);

    int total = Nn * C_OUT;
    init_agg<<<(total + 255) / 256, 256>>>(total);

    dim3 grid1((Nn + TM - 1) / TM, 2);
    k1_node_gemm<<<grid1, NTHR, shmem>>>(x, b1, Nn);

    long long EN = E + Nn;
    int nblk2 = (int)((EN + TM - 1) / TM);
    k2_edge_gemm<<<nblk2, NTHR, shmem>>>(E, Nn);

    k3_out_gemm<<<(Nn + TM - 1) / TM, NTHR, shmem>>>(b3, out, Nn);
}